// round 15
// baseline (speedup 1.0000x reference)
#include <cuda_runtime.h>
#include <cuda_bf16.h>
#include <cuda_fp16.h>
#include <math.h>
#include <stdint.h>

// ---------------- problem constants ----------------
constexpr int B = 16, S = 512, D = 768, H = 12, FF = 3072, L = 4;
constexpr int DH = 64;
constexpr int NREL = 129;
constexpr int NRELP = 144;
constexpr float SCALE = 0.125f;
constexpr float LN_EPS = 1e-12f;

constexpr size_t BS   = (size_t)B * S;
constexpr size_t BSD  = BS * D;
constexpr size_t BHS  = (size_t)B * H * S;
constexpr size_t BHSS = BHS * S;

// ---------------- device scratch ----------------
__device__ float g_x[BSD];
__device__ float g_qtab[BHS * NREL];
__device__ float g_ctx[BSD];
__device__ float g_tmp[BSD];
__device__ float g_attn[BSD];

constexpr size_t WSZ = (size_t)L * D * D;
constexpr size_t WFF = (size_t)L * FF * D;
__device__ __align__(256) __half g_scoresh[BHSS];
__device__ __align__(256) __half g_wqf[WSZ], g_wkf[WSZ], g_wvf[WSZ], g_wof[WSZ];
__device__ __align__(256) __half g_wif[WFF], g_wdf[WFF];
__device__ __align__(256) __half g_xf[BSD], g_ctxf[BSD], g_attnf[BSD];
__device__ __align__(256) __half g_fff[BS * FF];
__device__ __align__(256) __half g_qf[BSD], g_kf[BSD], g_vf[BSD];
__device__ __align__(256) __half g_pf[BHSS];
__device__ __align__(256) __half g_ptf[BHS * NRELP];
__device__ __align__(256) __half g_tabf[160 * 64];
__device__ __align__(256) __half g_tTf[64 * NRELP];

// ---------------- helpers ----------------
__device__ __forceinline__ float block_sum_fast(float v, float* red, float* bc) {
    int lane = threadIdx.x & 31, wid = threadIdx.x >> 5;
    #pragma unroll
    for (int o = 16; o > 0; o >>= 1) v += __shfl_xor_sync(0xffffffffu, v, o);
    if (lane == 0) red[wid] = v;
    __syncthreads();
    if (wid == 0) {
        float s = (lane < 8) ? red[lane] : 0.f;
        #pragma unroll
        for (int o = 4; o > 0; o >>= 1) s += __shfl_xor_sync(0xffffffffu, s, o);
        if (lane == 0) bc[0] = s;
    }
    __syncthreads();
    return bc[0];
}

__global__ void build_tables(const float* __restrict__ rel,
                             __half* __restrict__ tabf, __half* __restrict__ tTf)
{
    int i = blockIdx.x * 256 + threadIdx.x;
    if (i >= 160 * 64) return;
    int j = i / 64, d = i % 64;
    float v = (j < NREL) ? rel[((size_t)128 * S + (64 + j)) * DH + d] : 0.f;
    __half h = __float2half_rn(v);
    tabf[j * 64 + d] = h;
    if (j < NRELP) tTf[d * NRELP + j] = h;
}

__global__ __launch_bounds__(256) void conv_f16(
    const float* __restrict__ in, __half* __restrict__ o, int n4)
{
    int i = blockIdx.x * 256 + threadIdx.x;
    if (i >= n4) return;
    float4 v = ((const float4*)in)[i];
    __half2* op = (__half2*)o;
    op[i * 2 + 0] = __floats2half2_rn(v.x, v.y);
    op[i * 2 + 1] = __floats2half2_rn(v.z, v.w);
}

// ---------------- mma primitives ----------------
__device__ __forceinline__ void mma16816h(float* d, const uint32_t* a, const uint32_t* b) {
    asm volatile(
        "mma.sync.aligned.m16n8k16.row.col.f32.f16.f16.f32 "
        "{%0,%1,%2,%3}, {%4,%5,%6,%7}, {%8,%9}, {%0,%1,%2,%3};\n"
        : "+f"(d[0]), "+f"(d[1]), "+f"(d[2]), "+f"(d[3])
        : "r"(a[0]), "r"(a[1]), "r"(a[2]), "r"(a[3]), "r"(b[0]), "r"(b[1]));
}
__device__ __forceinline__ void ldsm4(uint32_t* r, uint32_t addr) {
    asm volatile("ldmatrix.sync.aligned.m8n8.x4.shared.b16 {%0,%1,%2,%3}, [%4];\n"
        : "=r"(r[0]), "=r"(r[1]), "=r"(r[2]), "=r"(r[3]) : "r"(addr));
}
__device__ __forceinline__ void ldsm4t(uint32_t* r, uint32_t addr) {
    asm volatile("ldmatrix.sync.aligned.m8n8.x4.trans.shared.b16 {%0,%1,%2,%3}, [%4];\n"
        : "=r"(r[0]), "=r"(r[1]), "=r"(r[2]), "=r"(r[3]) : "r"(addr));
}
__device__ __forceinline__ void cp16(uint32_t dst, const void* src) {
    asm volatile("cp.async.cg.shared.global [%0], [%1], 16;\n" :: "r"(dst), "l"(src));
}
__device__ __forceinline__ void cp_commit() { asm volatile("cp.async.commit_group;\n"); }
__device__ __forceinline__ void cp_wait1() { asm volatile("cp.async.wait_group 1;\n" ::: "memory"); }
__device__ __forceinline__ void cp_wait0() { asm volatile("cp.async.wait_group 0;\n" ::: "memory"); }
__device__ __forceinline__ uint32_t smem_u32(const void* p) {
    return (uint32_t)__cvta_generic_to_shared(p);
}

// ======================================================================
// fp16 single-term pipelined MMA GEMM NT (128x128 tile)
// ======================================================================
constexpr int FSTR = 40;
constexpr int FARR = 128 * FSTR * 2;
constexpr int FSTG = 2 * FARR;
constexpr int FNSTG = 3;
constexpr int F_SMEM = FNSTG * FSTG;

struct F16Targets {
    const __half* w[3];
    const float* bias[3];
    const float* res[3];
    float* c[3];
    __half* cf[3];
};

__global__ __launch_bounds__(256, 2) void gemm_f16_pipe(
    const __half* __restrict__ A, F16Targets tg, int M, int N, int K, int act)
{
    extern __shared__ __align__(16) char dsm[];
    const uint32_t sbase = smem_u32(dsm);
    const int z = blockIdx.z;
    const __half* W = tg.w[z];

    const int bm = blockIdx.y * 128, bn = blockIdx.x * 128;
    const int t = threadIdx.x, lane = t & 31, w = t >> 5;
    const int wm = (w & 1) * 64, wn = (w >> 1) * 32;

    float acc[4][4][4];
    #pragma unroll
    for (int i = 0; i < 4; i++)
        #pragma unroll
        for (int j = 0; j < 4; j++)
            #pragma unroll
            for (int r = 0; r < 4; r++) acc[i][j][r] = 0.f;

    uint32_t aoff[4], boff[2];
    #pragma unroll
    for (int mi = 0; mi < 4; mi++)
        aoff[mi] = (uint32_t)(((wm + mi * 16 + (lane & 15)) * FSTR + ((lane >> 4) << 3)) * 2);
    #pragma unroll
    for (int ni2 = 0; ni2 < 2; ni2++)
        boff[ni2] = (uint32_t)(((wn + ni2 * 16 + (lane & 7) + ((lane >> 4) << 3)) * FSTR
                               + (((lane >> 3) & 1) << 3)) * 2);

    const int nk = K / 32;
    const int r0 = t >> 2, c0 = t & 3;
    const int r1 = (t + 256) >> 2, c1 = (t + 256) & 3;
    const uint32_t d0 = (uint32_t)((r0 * FSTR + c0 * 8) * 2);
    const uint32_t d1 = (uint32_t)((r1 * FSTR + c1 * 8) * 2);

    auto issue = [&](int c) {
        if (c < nk) {
            const uint32_t base = sbase + (c % FNSTG) * FSTG;
            const size_t k0 = (size_t)c * 32;
            cp16(base + d0,        A + (size_t)(bm + r0) * K + k0 + c0 * 8);
            cp16(base + d1,        A + (size_t)(bm + r1) * K + k0 + c1 * 8);
            cp16(base + FARR + d0, W + (size_t)(bn + r0) * K + k0 + c0 * 8);
            cp16(base + FARR + d1, W + (size_t)(bn + r1) * K + k0 + c1 * 8);
        }
        cp_commit();
    };
    issue(0);
    issue(1);

    for (int kt = 0; kt < nk; kt++) {
        cp_wait1();
        __syncthreads();
        issue(kt + 2);

        const uint32_t sb = sbase + (kt % FNSTG) * FSTG;
        #pragma unroll
        for (int kk2 = 0; kk2 < 2; kk2++) {
            const uint32_t ko = kk2 * 32;
            uint32_t ah[4][4], bh[4][2];
            #pragma unroll
            for (int mi = 0; mi < 4; mi++)
                ldsm4(ah[mi], sb + aoff[mi] + ko);
            #pragma unroll
            for (int ni2 = 0; ni2 < 2; ni2++) {
                uint32_t t4[4];
                ldsm4(t4, sb + FARR + boff[ni2] + ko);
                bh[ni2 * 2][0] = t4[0]; bh[ni2 * 2][1] = t4[1];
                bh[ni2 * 2 + 1][0] = t4[2]; bh[ni2 * 2 + 1][1] = t4[3];
            }
            #pragma unroll
            for (int mi = 0; mi < 4; mi++)
                #pragma unroll
                for (int ni = 0; ni < 4; ni++)
                    mma16816h(acc[mi][ni], ah[mi], bh[ni]);
        }
        __syncthreads();
    }

    const float* bias = tg.bias[z];
    const float* res  = tg.res[z];
    float* Cp = tg.c[z];
    __half* Cf = tg.cf[z];

    #pragma unroll
    for (int mi = 0; mi < 4; mi++) {
        int m0 = bm + wm + mi * 16 + (lane >> 2);
        #pragma unroll
        for (int ni = 0; ni < 4; ni++) {
            int n = bn + wn + ni * 8 + (lane & 3) * 2;
            float2 v0 = make_float2(acc[mi][ni][0], acc[mi][ni][1]);
            float2 v1 = make_float2(acc[mi][ni][2], acc[mi][ni][3]);
            if (bias) {
                float2 bv = *(const float2*)&bias[n];
                v0.x += bv.x; v0.y += bv.y; v1.x += bv.x; v1.y += bv.y;
            }
            if (res) {
                float2 rr0 = *(const float2*)&res[(size_t)m0 * N + n];
                float2 rr1 = *(const float2*)&res[(size_t)(m0 + 8) * N + n];
                v0.x += rr0.x; v0.y += rr0.y; v1.x += rr1.x; v1.y += rr1.y;
            }
            if (act == 1) {
                v0.x = 0.5f * v0.x * (1.f + erff(v0.x * 0.70710678118654752f));
                v0.y = 0.5f * v0.y * (1.f + erff(v0.y * 0.70710678118654752f));
                v1.x = 0.5f * v1.x * (1.f + erff(v1.x * 0.70710678118654752f));
                v1.y = 0.5f * v1.y * (1.f + erff(v1.y * 0.70710678118654752f));
            }
            if (Cp) {
                *(float2*)&Cp[(size_t)m0 * N + n] = v0;
                *(float2*)&Cp[(size_t)(m0 + 8) * N + n] = v1;
            }
            if (Cf) {
                *(__half2*)&Cf[(size_t)m0 * N + n] = __floats2half2_rn(v0.x, v0.y);
                *(__half2*)&Cf[(size_t)(m0 + 8) * N + n] = __floats2half2_rn(v1.x, v1.y);
            }
        }
    }
}

// ======================================================================
// fp16 GEMM NT, 64x128 tile (wave-quantization variant for 384-CTA shapes)
// 8 warps 2m x 4n, warp tile 32x32, k32, 3-stage cp.async. Single target,
// fp32 out with bias+res.
// ======================================================================
constexpr int G64_A = 64 * FSTR * 2;          // 5120 B
constexpr int G64_B = 128 * FSTR * 2;         // 10240 B
constexpr int G64_STG = G64_A + G64_B;        // 15360
constexpr int G64_SMEM = FNSTG * G64_STG;     // 46080

__global__ __launch_bounds__(256, 2) void gemm_f16_pipe64(
    const __half* __restrict__ A, const __half* __restrict__ W,
    const float* __restrict__ bias, const float* __restrict__ res,
    float* __restrict__ Cp, int M, int N, int K)
{
    extern __shared__ __align__(16) char dsm[];
    const uint32_t sbase = smem_u32(dsm);
    const int bm = blockIdx.y * 64, bn = blockIdx.x * 128;
    const int t = threadIdx.x, lane = t & 31, w = t >> 5;
    const int wm = (w & 1) * 32, wn = (w >> 1) * 32;

    float acc[2][4][4];
    #pragma unroll
    for (int i = 0; i < 2; i++)
        #pragma unroll
        for (int j = 0; j < 4; j++)
            #pragma unroll
            for (int r = 0; r < 4; r++) acc[i][j][r] = 0.f;

    uint32_t aoff[2], boff[2];
    #pragma unroll
    for (int mi = 0; mi < 2; mi++)
        aoff[mi] = (uint32_t)(((wm + mi * 16 + (lane & 15)) * FSTR + ((lane >> 4) << 3)) * 2);
    #pragma unroll
    for (int ni2 = 0; ni2 < 2; ni2++)
        boff[ni2] = (uint32_t)(((wn + ni2 * 16 + (lane & 7) + ((lane >> 4) << 3)) * FSTR
                               + (((lane >> 3) & 1) << 3)) * 2);

    const int nk = K / 32;
    // A: 256 segs (1/thread); B: 512 segs (2/thread)
    const int ar = t >> 2, ac = (t & 3) * 8;
    const uint32_t ad = (uint32_t)((ar * FSTR + ac) * 2);
    const int br0 = t >> 2, bc0 = (t & 3) * 8;
    const int br1 = (t + 256) >> 2, bc1 = ((t + 256) & 3) * 8;
    const uint32_t bd0 = (uint32_t)((br0 * FSTR + bc0) * 2);
    const uint32_t bd1 = (uint32_t)((br1 * FSTR + bc1) * 2);

    auto issue = [&](int c) {
        if (c < nk) {
            const uint32_t base = sbase + (c % FNSTG) * G64_STG;
            const size_t k0 = (size_t)c * 32;
            cp16(base + ad,               A + (size_t)(bm + ar) * K + k0 + ac);
            cp16(base + G64_A + bd0,      W + (size_t)(bn + br0) * K + k0 + bc0);
            cp16(base + G64_A + bd1,      W + (size_t)(bn + br1) * K + k0 + bc1);
        }
        cp_commit();
    };
    issue(0);
    issue(1);

    for (int kt = 0; kt < nk; kt++) {
        cp_wait1();
        __syncthreads();
        issue(kt + 2);

        const uint32_t sb = sbase + (kt % FNSTG) * G64_STG;
        #pragma unroll
        for (int kk2 = 0; kk2 < 2; kk2++) {
            const uint32_t ko = kk2 * 32;
            uint32_t ah[2][4], bh[4][2];
            #pragma unroll
            for (int mi = 0; mi < 2; mi++)
                ldsm4(ah[mi], sb + aoff[mi] + ko);
            #pragma unroll
            for (int ni2 = 0; ni2 < 2; ni2++) {
                uint32_t t4[4];
                ldsm4(t4, sb + G64_A + boff[ni2] + ko);
                bh[ni2 * 2][0] = t4[0]; bh[ni2 * 2][1] = t4[1];
                bh[ni2 * 2 + 1][0] = t4[2]; bh[ni2 * 2 + 1][1] = t4[3];
            }
            #pragma unroll
            for (int mi = 0; mi < 2; mi++)
                #pragma unroll
                for (int ni = 0; ni < 4; ni++)
                    mma16816h(acc[mi][ni], ah[mi], bh[ni]);
        }
        __syncthreads();
    }

    #pragma unroll
    for (int mi = 0; mi < 2; mi++) {
        int m0 = bm + wm + mi * 16 + (lane >> 2);
        #pragma unroll
        for (int ni = 0; ni < 4; ni++) {
            int n = bn + wn + ni * 8 + (lane & 3) * 2;
            float2 v0 = make_float2(acc[mi][ni][0], acc[mi][ni][1]);
            float2 v1 = make_float2(acc[mi][ni][2], acc[mi][ni][3]);
            float2 bv = *(const float2*)&bias[n];
            v0.x += bv.x; v0.y += bv.y; v1.x += bv.x; v1.y += bv.y;
            float2 rr0 = *(const float2*)&res[(size_t)m0 * N + n];
            float2 rr1 = *(const float2*)&res[(size_t)(m0 + 8) * N + n];
            v0.x += rr0.x; v0.y += rr0.y; v1.x += rr1.x; v1.y += rr1.y;
            *(float2*)&Cp[(size_t)m0 * N + n] = v0;
            *(float2*)&Cp[(size_t)(m0 + 8) * N + n] = v1;
        }
    }
}

// ======================================================================
// qtab fp16
// ======================================================================
constexpr int QT_STR = 72;
constexpr int QT_A = 128 * QT_STR * 2;
constexpr int QT_B = 160 * QT_STR * 2;
constexpr int QT_SMEM = QT_A + QT_B;

__global__ __launch_bounds__(256) void qtab_f16(
    const __half* __restrict__ Qf, const __half* __restrict__ Tf,
    float* __restrict__ qt)
{
    extern __shared__ __align__(16) char dsm[];
    __half* sA = (__half*)dsm;
    __half* sB = (__half*)(dsm + QT_A);
    const uint32_t bA = smem_u32(sA), bB = smem_u32(sB);

    const int bm = blockIdx.x * 128;
    const int t = threadIdx.x, lane = t & 31, w = t >> 5;
    const int wm = (w & 3) * 32, wn = (w >> 2) * 80;

    #pragma unroll
    for (int i = 0; i < 4; i++) {
        int s = t + i * 256;
        int row = s >> 3, c8 = s & 7;
        *(uint4*)&sA[row * QT_STR + c8 * 8] = *(const uint4*)&Qf[(size_t)(bm + row) * 64 + c8 * 8];
    }
    #pragma unroll
    for (int i = 0; i < 5; i++) {
        int s = t + i * 256;
        int row = s >> 3, c8 = s & 7;
        *(uint4*)&sB[row * QT_STR + c8 * 8] = *(const uint4*)&Tf[row * 64 + c8 * 8];
    }
    __syncthreads();

    float acc[2][10][4];
    #pragma unroll
    for (int i = 0; i < 2; i++)
        #pragma unroll
        for (int j = 0; j < 10; j++)
            #pragma unroll
            for (int r = 0; r < 4; r++) acc[i][j][r] = 0.f;

    uint32_t aoff[2], boff[5];
    #pragma unroll
    for (int mi = 0; mi < 2; mi++)
        aoff[mi] = (uint32_t)(((wm + mi * 16 + (lane & 15)) * QT_STR + ((lane >> 4) << 3)) * 2);
    #pragma unroll
    for (int ni2 = 0; ni2 < 5; ni2++)
        boff[ni2] = (uint32_t)(((wn + ni2 * 16 + (lane & 7) + ((lane >> 4) << 3)) * QT_STR
                               + (((lane >> 3) & 1) << 3)) * 2);

    #pragma unroll
    for (int kc = 0; kc < 4; kc++) {
        uint32_t ko = kc * 32;
        uint32_t ah[2][4];
        #pragma unroll
        for (int mi = 0; mi < 2; mi++)
            ldsm4(ah[mi], bA + aoff[mi] + ko);
        #pragma unroll
        for (int ni2 = 0; ni2 < 5; ni2++) {
            uint32_t t4[4];
            ldsm4(t4, bB + boff[ni2] + ko);
            uint32_t b0[2] = {t4[0], t4[1]}, b1[2] = {t4[2], t4[3]};
            #pragma unroll
            for (int mi = 0; mi < 2; mi++) {
                mma16816h(acc[mi][ni2 * 2], ah[mi], b0);
                mma16816h(acc[mi][ni2 * 2 + 1], ah[mi], b1);
            }
        }
    }

    #pragma unroll
    for (int mi = 0; mi < 2; mi++)
        #pragma unroll
        for (int rr = 0; rr < 2; rr++) {
            int m0 = bm + wm + mi * 16 + (lane >> 2) + rr * 8;
            #pragma unroll
            for (int ni = 0; ni < 10; ni++) {
                int n = wn + ni * 8 + (lane & 3) * 2;
                if (n < NREL)     qt[(size_t)m0 * NREL + n]     = acc[mi][ni][rr * 2 + 0];
                if (n + 1 < NREL) qt[(size_t)m0 * NREL + n + 1] = acc[mi][ni][rr * 2 + 1];
            }
        }
}

// ======================================================================
// ctx_rel fp16
// ======================================================================
constexpr int CR_ASTR = 56;
constexpr int CR_BSTR = 152;
constexpr int CR_A = 128 * CR_ASTR * 2;
constexpr int CR_B = 64 * CR_BSTR * 2;
constexpr int CR_SMEM = CR_A + CR_B;

__global__ __launch_bounds__(256) void ctx_rel_f16(
    const __half* __restrict__ Pf, const __half* __restrict__ Tf,
    float* __restrict__ ctx)
{
    extern __shared__ __align__(16) char dsm[];
    __half* sA = (__half*)dsm;
    __half* sB = (__half*)(dsm + CR_A);
    const uint32_t bA = smem_u32(sA), bB = smem_u32(sB);

    const int bm = blockIdx.x * 128;
    const int t = threadIdx.x, lane = t & 31, w = t >> 5;
    const int wm = (w & 3) * 32, wn = (w >> 2) * 32;

    for (int s = t; s < 1152; s += 256) {
        int row = s / 18, c8 = s % 18;
        *(uint4*)&sB[row * CR_BSTR + c8 * 8] = *(const uint4*)&Tf[row * NRELP + c8 * 8];
    }

    float acc[2][4][4];
    #pragma unroll
    for (int i = 0; i < 2; i++)
        #pragma unroll
        for (int j = 0; j < 4; j++)
            #pragma unroll
            for (int r = 0; r < 4; r++) acc[i][j][r] = 0.f;

    uint32_t aoff[2], boff[2];
    #pragma unroll
    for (int mi = 0; mi < 2; mi++)
        aoff[mi] = (uint32_t)(((wm + mi * 16 + (lane & 15)) * CR_ASTR + ((lane >> 4) << 3)) * 2);
    #pragma unroll
    for (int ni2 = 0; ni2 < 2; ni2++)
        boff[ni2] = (uint32_t)(((wn + ni2 * 16 + (lane & 7) + ((lane >> 4) << 3)) * CR_BSTR
                               + (((lane >> 3) & 1) << 3)) * 2);

    for (int c = 0; c < 3; c++) {
        __syncthreads();
        #pragma unroll
        for (int i = 0; i < 3; i++) {
            int s = t + i * 256;
            int row = s / 6, c8 = s % 6;
            size_t src = (size_t)(bm + row) * NRELP + c * 48 + c8 * 8;
            *(uint4*)&sA[row * CR_ASTR + c8 * 8] = *(const uint4*)&Pf[src];
        }
        __syncthreads();
        #pragma unroll
        for (int kc = 0; kc < 3; kc++) {
            uint32_t kaoff = kc * 32;
            uint32_t kboff = (uint32_t)(c * 96 + kc * 32);
            uint32_t ah[2][4];
            #pragma unroll
            for (int mi = 0; mi < 2; mi++)
                ldsm4(ah[mi], bA + aoff[mi] + kaoff);
            #pragma unroll
            for (int ni2 = 0; ni2 < 2; ni2++) {
                uint32_t t4[4];
                ldsm4(t4, bB + boff[ni2] + kboff);
                uint32_t b0[2] = {t4[0], t4[1]}, b1[2] = {t4[2], t4[3]};
                #pragma unroll
                for (int mi = 0; mi < 2; mi++) {
                    mma16816h(acc[mi][ni2 * 2], ah[mi], b0);
                    mma16816h(acc[mi][ni2 * 2 + 1], ah[mi], b1);
                }
            }
        }
    }

    #pragma unroll
    for (int mi = 0; mi < 2; mi++)
        #pragma unroll
        for (int rr = 0; rr < 2; rr++) {
            int m0 = bm + wm + mi * 16 + (lane >> 2) + rr * 8;
            #pragma unroll
            for (int ni = 0; ni < 4; ni++) {
                int n = wn + ni * 8 + (lane & 3) * 2;
                float2 v = make_float2(acc[mi][ni][rr * 2 + 0], acc[mi][ni][rr * 2 + 1]);
                *(float2*)&ctx[(size_t)m0 * 64 + n] = v;
            }
        }
}

// ======================================================================
// Scores fp16 -> fp16 score storage
// ======================================================================
constexpr int QSTR = 40;
constexpr int SC_ARR = 128 * QSTR * 2;
constexpr int SC_STG = 2 * SC_ARR;
constexpr int SC_SMEM = 2 * SC_STG;

__global__ __launch_bounds__(256) void scores_f16(
    const __half* __restrict__ Qf, const __half* __restrict__ Kf,
    const float* __restrict__ qtab, const int* __restrict__ mask,
    __half* __restrict__ scores)
{
    extern __shared__ __align__(16) char dsm[];
    const uint32_t sbase = smem_u32(dsm);
    const int bh = blockIdx.z, b = bh / H, h = bh % H;
    const int q0 = blockIdx.y * 128, k0b = blockIdx.x * 128;
    const int t = threadIdx.x, lane = t & 31, w = t >> 5;
    const int wm = (w & 1) * 64, wn = (w >> 1) * 32;

    float acc[4][4][4];
    #pragma unroll
    for (int i = 0; i < 4; i++)
        #pragma unroll
        for (int j = 0; j < 4; j++)
            #pragma unroll
            for (int r = 0; r < 4; r++) acc[i][j][r] = 0.f;

    uint32_t aoff[4], boff[2];
    #pragma unroll
    for (int mi = 0; mi < 4; mi++)
        aoff[mi] = (uint32_t)(((wm + mi * 16 + (lane & 15)) * QSTR + ((lane >> 4) << 3)) * 2);
    #pragma unroll
    for (int ni2 = 0; ni2 < 2; ni2++)
        boff[ni2] = (uint32_t)(((wn + ni2 * 16 + (lane & 7) + ((lane >> 4) << 3)) * QSTR
                               + (((lane >> 3) & 1) << 3)) * 2);

    auto issue = [&](int kt) {
        uint32_t base = sbase + kt * SC_STG;
        #pragma unroll
        for (int i = 0; i < 2; i++) {
            int idx = t * 2 + i;
            int row = idx >> 2, cseg = (idx & 3) * 8;
            size_t qsrc = ((size_t)(b * S) + q0 + row) * D + h * DH + kt * 32 + cseg;
            size_t ksrc = ((size_t)(b * S) + k0b + row) * D + h * DH + kt * 32 + cseg;
            uint32_t d = base + (uint32_t)((row * QSTR + cseg) * 2);
            cp16(d,          Qf + qsrc);
            cp16(d + SC_ARR, Kf + ksrc);
        }
        cp_commit();
    };
    issue(0);
    issue(1);

    for (int kt = 0; kt < 2; kt++) {
        if (kt == 0) cp_wait1(); else cp_wait0();
        __syncthreads();
        const uint32_t sb = sbase + kt * SC_STG;
        #pragma unroll
        for (int kk2 = 0; kk2 < 2; kk2++) {
            uint32_t koffb = kk2 * 32;
            uint32_t ah[4][4], bh2[4][2];
            #pragma unroll
            for (int mi = 0; mi < 4; mi++)
                ldsm4(ah[mi], sb + aoff[mi] + koffb);
            #pragma unroll
            for (int ni2 = 0; ni2 < 2; ni2++) {
                uint32_t t4[4];
                ldsm4(t4, sb + SC_ARR + boff[ni2] + koffb);
                bh2[ni2 * 2][0] = t4[0]; bh2[ni2 * 2][1] = t4[1];
                bh2[ni2 * 2 + 1][0] = t4[2]; bh2[ni2 * 2 + 1][1] = t4[3];
            }
            #pragma unroll
            for (int mi = 0; mi < 4; mi++)
                #pragma unroll
                for (int ni = 0; ni < 4; ni++)
                    mma16816h(acc[mi][ni], ah[mi], bh2[ni]);
        }
    }

    #pragma unroll
    for (int mi = 0; mi < 4; mi++) {
        #pragma unroll
        for (int rr = 0; rr < 2; rr++) {
            int q = q0 + wm + mi * 16 + (lane >> 2) + rr * 8;
            const float* qtr = qtab + (((size_t)b * S + q) * H + h) * NREL;
            size_t rowb = ((size_t)bh * S + q) * S;
            #pragma unroll
            for (int ni = 0; ni < 4; ni++) {
                int k = k0b + wn + ni * 8 + (lane & 3) * 2;
                float vx = acc[mi][ni][rr * 2 + 0];
                float vy = acc[mi][ni][rr * 2 + 1];
                int r0 = k - q; r0 = r0 < -64 ? -64 : (r0 > 64 ? 64 : r0);
                int r1 = k + 1 - q; r1 = r1 < -64 ? -64 : (r1 > 64 ? 64 : r1);
                float mb0 = (1.f - (float)mask[b * S + k]) * -10000.f;
                float mb1 = (1.f - (float)mask[b * S + k + 1]) * -10000.f;
                float ox = (vx + qtr[r0 + 64]) * SCALE + mb0;
                float oy = (vy + qtr[r1 + 64]) * SCALE + mb1;
                *(__half2*)&scores[rowb + k] = __floats2half2_rn(ox, oy);
            }
        }
    }
}

// ======================================================================
// ctx_pv fp16
// ======================================================================
constexpr int VSTR = 72;
constexpr int PV_P = 128 * QSTR * 2;
constexpr int PV_V = 32 * VSTR * 2;
constexpr int PV_STG = PV_P + PV_V;
constexpr int PV_NSTG = 3;
constexpr int PV_SMEM = PV_NSTG * PV_STG;

__global__ __launch_bounds__(256) void ctx_pv_f16(
    const __half* __restrict__ Pf, const __half* __restrict__ Vf,
    const float* __restrict__ ctxin, __half* __restrict__ outf)
{
    extern __shared__ __align__(16) char dsm[];
    const uint32_t sbase = smem_u32(dsm);
    const int bh = blockIdx.z, b = bh / H, h = bh % H;
    const int q0 = blockIdx.x * 128;
    const int t = threadIdx.x, lane = t & 31, w = t >> 5;
    const int wm = (w & 3) * 32, wn = (w >> 2) * 32;

    float acc[2][4][4];
    #pragma unroll
    for (int i = 0; i < 2; i++)
        #pragma unroll
        for (int j = 0; j < 4; j++)
            #pragma unroll
            for (int r = 0; r < 4; r++) acc[i][j][r] = 0.f;

    uint32_t aoff[2];
    #pragma unroll
    for (int mi = 0; mi < 2; mi++)
        aoff[mi] = (uint32_t)(((wm + mi * 16 + (lane & 15)) * QSTR + ((lane >> 4) << 3)) * 2);

    const int nk = S / 32;

    auto issue = [&](int kt, int slot) {
        if (kt < nk) {
            uint32_t base = sbase + slot * PV_STG;
            #pragma unroll
            for (int i = 0; i < 2; i++) {
                int idx = t * 2 + i;
                int row = idx >> 2, cseg = (idx & 3) * 8;
                size_t psrc = ((size_t)bh * S + q0 + row) * S + kt * 32 + cseg;
                cp16(base + (uint32_t)((row * QSTR + cseg) * 2), Pf + psrc);
            }
            {
                int row = t >> 3, cseg = (t & 7) * 8;
                size_t vsrc = ((size_t)(b * S) + kt * 32 + row) * D + h * DH + cseg;
                cp16(base + PV_P + (uint32_t)((row * VSTR + cseg) * 2), Vf + vsrc);
            }
        }
        cp_commit();
    };
    issue(0, 0);
    issue(1, 1);

    for (int kt = 0; kt < nk; kt++) {
        cp_wait1();
        __syncthreads();
        issue(kt + 2, (kt + 2) % PV_NSTG);

        const uint32_t sb = sbase + (kt % PV_NSTG) * PV_STG;
        #pragma unroll
        for (int kk2 = 0; kk2 < 2; kk2++) {
            uint32_t koffb = kk2 * 32;
            uint32_t ah[2][4], bh2[4][2];
            #pragma unroll
            for (int mi = 0; mi < 2; mi++)
                ldsm4(ah[mi], sb + aoff[mi] + koffb);
            #pragma unroll
            for (int ni2 = 0; ni2 < 2; ni2++) {
                uint32_t vaddr = (uint32_t)(((kk2 * 16 + (lane & 15)) * VSTR
                                 + wn + ni2 * 16 + (lane >> 4) * 8) * 2);
                uint32_t t4[4];
                ldsm4t(t4, sb + PV_P + vaddr);
                bh2[ni2 * 2][0] = t4[0]; bh2[ni2 * 2][1] = t4[1];
                bh2[ni2 * 2 + 1][0] = t4[2]; bh2[ni2 * 2 + 1][1] = t4[3];
            }
            #pragma unroll
            for (int mi = 0; mi < 2; mi++)
                #pragma unroll
                for (int ni = 0; ni < 4; ni++)
                    mma16816h(acc[mi][ni], ah[mi], bh2[ni]);
        }
        __syncthreads();
    }

    #pragma unroll
    for (int mi = 0; mi < 2; mi++) {
        #pragma unroll
        for (int rr = 0; rr < 2; rr++) {
            int q = q0 + wm + mi * 16 + (lane >> 2) + rr * 8;
            size_t rb = ((size_t)(b * S) + q) * D + h * DH;
            #pragma unroll
            for (int ni = 0; ni < 4; ni++) {
                int d = wn + ni * 8 + (lane & 3) * 2;
                float2 cur = *(const float2*)&ctxin[rb + d];
                cur.x += acc[mi][ni][rr * 2 + 0];
                cur.y += acc[mi][ni][rr * 2 + 1];
                *(__half2*)&outf[rb + d] = __floats2half2_rn(cur.x, cur.y);
            }
        }
    }
}

// ---------------- embedding + LN (fast shuffle reductions) ----------------
__global__ __launch_bounds__(256) void embed_ln(
    const int* __restrict__ ids, const int* __restrict__ tti,
    const float* __restrict__ we, const float* __restrict__ te,
    const float* __restrict__ w, const float* __restrict__ bb,
    float* __restrict__ out, __half* __restrict__ of)
{
    __shared__ float red[8];
    __shared__ float bc0[1], bc1[1];
    int m = blockIdx.x, t = threadIdx.x;
    int id = ids[m], t2 = tti[m];
    const float* wr = we + (size_t)id * D;
    const float* tr = te + (size_t)t2 * D;
    float vals[3]; float s = 0.f;
    #pragma unroll
    for (int i = 0; i < 3; i++) { int d = t + i * 256; vals[i] = wr[d] + tr[d]; s += vals[i]; }
    float mean = block_sum_fast(s, red, bc0) * (1.f / D);
    float vs = 0.f;
    #pragma unroll
    for (int i = 0; i < 3; i++) { float dd = vals[i] - mean; vs += dd * dd; }
    float var = block_sum_fast(vs, red, bc1) * (1.f / D);
    float rstd = rsqrtf(var + LN_EPS);
    #pragma unroll
    for (int i = 0; i < 3; i++) {
        int d = t + i * 256;
        float v = (vals[i] - mean) * rstd * w[d] + bb[d];
        out[(size_t)m * D + d] = v;
        of[(size_t)m * D + d] = __float2half_rn(v);
    }
}

__global__ __launch_bounds__(256) void ln_kernel(
    const float* __restrict__ x, const float* __restrict__ w,
    const float* __restrict__ bb, float* __restrict__ out,
    __half* __restrict__ of)
{
    __shared__ float red[8];
    __shared__ float bc0[1], bc1[1];
    int m = blockIdx.x, t = threadIdx.x;
    const float* xr = x + (size_t)m * D;
    float vals[3]; float s = 0.f;
    #pragma unroll
    for (int i = 0; i < 3; i++) { vals[i] = xr[t + i * 256]; s += vals[i]; }
    float mean = block_sum_fast(s, red, bc0) * (1.f / D);
    float vs = 0.f;
    #pragma unroll
    for (int i = 0; i < 3; i++) { float dd = vals[i] - mean; vs += dd * dd; }
    float var = block_sum_fast(vs, red, bc1) * (1.f / D);
    float rstd = rsqrtf(var + LN_EPS);
    #pragma unroll
    for (int i = 0; i < 3; i++) {
        int d = t + i * 256;
        float v = (vals[i] - mean) * rstd * w[d] + bb[d];
        out[(size_t)m * D + d] = v;
        of[(size_t)m * D + d] = __float2half_rn(v);
    }
}

// ---------------- warp-per-row softmax (fp16 score input) ----------------
__global__ __launch_bounds__(256) void softmax_warp(
    const __half* __restrict__ scores,
    __half* __restrict__ pf, __half* __restrict__ ptf)
{
    __shared__ float srow[8][512];
    const int w = threadIdx.x >> 5, lane = threadIdx.x & 31;
    const int row = blockIdx.x * 8 + w;
    const int q = row % S, bh = row / S;
    const int b = bh / H, h = bh % H;
    const __half* sr = scores + (size_t)row * S;

    float2 v[8];
    float m = -1e30f;
    #pragma unroll
    for (int i = 0; i < 8; i++) {
        __half2 h2 = *(const __half2*)&sr[lane * 2 + 64 * i];
        v[i] = __half22float2(h2);
        m = fmaxf(m, fmaxf(v[i].x, v[i].y));
    }
    #pragma unroll
    for (int o = 16; o > 0; o >>= 1) m = fmaxf(m, __shfl_xor_sync(0xffffffffu, m, o));

    float s = 0.f;
    #pragma unroll
    for (int i = 0; i < 8; i++) {
        v[i].x = expf(v[i].x - m); v[i].y = expf(v[i].y - m);
        s += v[i].x + v[i].y;
    }
    #pragma unroll
    for (int o = 16; o > 0; o >>= 1) s += __shfl_xor_sync(0xffffffffu, s, o);
    float inv = 1.f / s;

    size_t rb = (size_t)row * S;
    float left = 0.f, right = 0.f;
    #pragma unroll
    for (int i = 0; i < 8; i++) {
        int k = lane * 2 + 64 * i;
        float p0 = v[i].x * inv, p1 = v[i].y * inv;
        srow[w][k] = p0; srow[w][k + 1] = p1;
        *(__half2*)&pf[rb + k] = __floats2half2_rn(p0, p1);
        if (k <= q - 64)     left += p0;
        if (k + 1 <= q - 64) left += p1;
        if (k >= q + 64)     right += p0;
        if (k + 1 >= q + 64) right += p1;
    }
    #pragma unroll
    for (int o = 16; o > 0; o >>= 1) {
        left  += __shfl_xor_sync(0xffffffffu, left, o);
        right += __shfl_xor_sync(0xffffffffu, right, o);
    }
    __syncwarp();

    size_t pbase = ((size_t)(b * S + q) * H + h) * NRELP;
    if (lane == 0) {
        ptf[pbase]       = __float2half_rn(left);
        ptf[pbase + 128] = __float2half_rn(right);
    }
    if (lane < 15) ptf[pbase + 129 + lane] = __float2half_rn(0.f);
    #pragma unroll
    for (int jj = 0; jj < 4; jj++) {
        int j = 1 + lane + 32 * jj;
        if (j <= 127) {
            int k = q + j - 64;
            float p = (k >= 0 && k < S) ? srow[w][k] : 0.f;
            ptf[pbase + j] = __float2half_rn(p);
        }
    }
}

// ---------------- launch ----------------
extern "C" void kernel_launch(void* const* d_in, const int* in_sizes, int n_in,
                              void* d_out, int out_size)
{
    const int*   ids     = (const int*)d_in[0];
    const int*   amask   = (const int*)d_in[1];
    const int*   tti     = (const int*)d_in[2];
    const float* wemb    = (const float*)d_in[3];
    const float* temb    = (const float*)d_in[4];
    const float* elnw    = (const float*)d_in[5];
    const float* elnb    = (const float*)d_in[6];
    const float* qw      = (const float*)d_in[7];
    const float* qb      = (const float*)d_in[8];
    const float* kw      = (const float*)d_in[9];
    const float* kb      = (const float*)d_in[10];
    const float* vw      = (const float*)d_in[11];
    const float* vb      = (const float*)d_in[12];
    const float* rel     = (const float*)d_in[13];
    const float* ow      = (const float*)d_in[14];
    const float* ob      = (const float*)d_in[15];
    const float* alnw    = (const float*)d_in[16];
    const float* alnb    = (const float*)d_in[17];
    const float* iw      = (const float*)d_in[18];
    const float* ib      = (const float*)d_in[19];
    const float* dw      = (const float*)d_in[20];
    const float* db      = (const float*)d_in[21];
    const float* olnw    = (const float*)d_in[22];
    const float* olnb    = (const float*)d_in[23];
    float* out = (float*)d_out;

    float *x, *qt, *ctx, *tmp, *attn;
    cudaGetSymbolAddress((void**)&x,    g_x);
    cudaGetSymbolAddress((void**)&qt,   g_qtab);
    cudaGetSymbolAddress((void**)&ctx,  g_ctx);
    cudaGetSymbolAddress((void**)&tmp,  g_tmp);
    cudaGetSymbolAddress((void**)&attn, g_attn);

    __half *scf;
    __half *wqf, *wkf, *wvf, *wof, *wif, *wdf, *xf, *ctxf, *attnf, *fff;
    __half *qf, *kf, *vf, *pf, *ptf, *tabf, *tTf;
    cudaGetSymbolAddress((void**)&scf, g_scoresh);
    cudaGetSymbolAddress((void**)&wqf, g_wqf);
    cudaGetSymbolAddress((void**)&wkf, g_wkf);
    cudaGetSymbolAddress((void**)&wvf, g_wvf);
    cudaGetSymbolAddress((void**)&wof, g_wof);
    cudaGetSymbolAddress((void**)&wif, g_wif);
    cudaGetSymbolAddress((void**)&wdf, g_wdf);
    cudaGetSymbolAddress((void**)&xf,   g_xf);
    cudaGetSymbolAddress((void**)&ctxf, g_ctxf);
    cudaGetSymbolAddress((void**)&attnf, g_attnf);
    cudaGetSymbolAddress((void**)&fff,  g_fff);
    cudaGetSymbolAddress((void**)&qf,  g_qf);
    cudaGetSymbolAddress((void**)&kf,  g_kf);
    cudaGetSymbolAddress((void**)&vf,  g_vf);
    cudaGetSymbolAddress((void**)&pf,  g_pf);
    cudaGetSymbolAddress((void**)&ptf, g_ptf);
    cudaGetSymbolAddress((void**)&tabf, g_tabf);
    cudaGetSymbolAddress((void**)&tTf,  g_tTf);

    cudaFuncSetAttribute(gemm_f16_pipe, cudaFuncAttributeMaxDynamicSharedMemorySize, F_SMEM);
    cudaFuncSetAttribute(gemm_f16_pipe64, cudaFuncAttributeMaxDynamicSharedMemorySize, G64_SMEM);
    cudaFuncSetAttribute(qtab_f16, cudaFuncAttributeMaxDynamicSharedMemorySize, QT_SMEM);
    cudaFuncSetAttribute(ctx_rel_f16, cudaFuncAttributeMaxDynamicSharedMemorySize, CR_SMEM);
    cudaFuncSetAttribute(scores_f16, cudaFuncAttributeMaxDynamicSharedMemorySize, SC_SMEM);
    cudaFuncSetAttribute(ctx_pv_f16, cudaFuncAttributeMaxDynamicSharedMemorySize, PV_SMEM);

    build_tables<<<(160 * 64 + 255) / 256, 256>>>(rel, tabf, tTf);
    embed_ln<<<(int)BS, 256>>>(ids, tti, wemb, temb, elnw, elnb, x, xf);

    {
        int n4 = (int)(WSZ / 4), g = (n4 + 255) / 256;
        conv_f16<<<g, 256>>>(qw, wqf, n4);
        conv_f16<<<g, 256>>>(kw, wkf, n4);
        conv_f16<<<g, 256>>>(vw, wvf, n4);
        conv_f16<<<g, 256>>>(ow, wof, n4);
        int n4f = (int)(WFF / 4), gf = (n4f + 255) / 256;
        conv_f16<<<gf, 256>>>(iw, wif, n4f);
        conv_f16<<<gf, 256>>>(dw, wdf, n4f);
    }

    const dim3 gQKV(D / 128, (int)(BS / 128), 3);
    const dim3 gP64(D / 128, (int)(BS / 64));          // (6,128) 64-row tiles
    const dim3 gF1(FF / 128, (int)(BS / 128), 1);
    const dim3 gSC(S / 128, S / 128, B * H);
    const dim3 gPV(S / 128, 1, B * H);
    const int gRow = (int)(BS * H / 128);

    for (int l = 0; l < L; l++) {
        const size_t wo = (size_t)l * D * D;
        const size_t fo = (size_t)l * FF * D;

        F16Targets tq = {};
        tq.w[0] = wqf + wo; tq.bias[0] = qb + l * D; tq.cf[0] = qf;
        tq.w[1] = wkf + wo; tq.bias[1] = kb + l * D; tq.cf[1] = kf;
        tq.w[2] = wvf + wo; tq.bias[2] = vb + l * D; tq.cf[2] = vf;
        gemm_f16_pipe<<<gQKV, 256, F_SMEM>>>(xf, tq, (int)BS, D, D, 0);

        qtab_f16<<<gRow, 256, QT_SMEM>>>(qf, tabf, qt);

        scores_f16<<<gSC, 256, SC_SMEM>>>(qf, kf, qt, amask, scf);
        softmax_warp<<<(int)(BHS / 8), 256>>>(scf, pf, ptf);

        ctx_rel_f16<<<gRow, 256, CR_SMEM>>>(ptf, tTf, ctx);
        ctx_pv_f16<<<gPV, 256, PV_SMEM>>>(pf, vf, ctx, ctxf);

        // O-proj: 64-row tile variant (wave-quantization fix)
        gemm_f16_pipe64<<<gP64, 256, G64_SMEM>>>(ctxf, wof + wo, ob + l * D,
                                                 x, tmp, (int)BS, D, D);
        ln_kernel<<<(int)BS, 256>>>(tmp, alnw + l * D, alnb + l * D, attn, attnf);

        F16Targets tf = {};
        tf.w[0] = wif + fo; tf.bias[0] = ib + l * FF; tf.cf[0] = fff;
        gemm_f16_pipe<<<gF1, 256, F_SMEM>>>(attnf, tf, (int)BS, FF, D, 1);

        // FFN2: 64-row tile variant
        gemm_f16_pipe64<<<gP64, 256, G64_SMEM>>>(fff, wdf + fo, db + l * D,
                                                 attn, tmp, (int)BS, D, FF);
        ln_kernel<<<(int)BS, 256>>>(tmp, olnw + l * D, olnb + l * D,
                                    (l == L - 1) ? out : x, xf);
    }
}

// round 16
// speedup vs baseline: 1.0562x; 1.0562x over previous
#include <cuda_runtime.h>
#include <cuda_bf16.h>
#include <cuda_fp16.h>
#include <math.h>
#include <stdint.h>

// ---------------- problem constants ----------------
constexpr int B = 16, S = 512, D = 768, H = 12, FF = 3072, L = 4;
constexpr int DH = 64;
constexpr int NREL = 129;
constexpr int NRELP = 144;
constexpr float SCALE = 0.125f;
constexpr float LN_EPS = 1e-12f;

constexpr size_t BS   = (size_t)B * S;
constexpr size_t BSD  = BS * D;
constexpr size_t BHS  = (size_t)B * H * S;
constexpr size_t BHSS = BHS * S;

// ---------------- device scratch ----------------
__device__ float g_x[BSD];
__device__ float g_qtab[BHS * NREL];
__device__ float g_ctx[BSD];
__device__ float g_tmpA[BSD];
__device__ float g_tmpB[BSD];
__device__ float g_attn[BSD];

constexpr size_t WSZ = (size_t)L * D * D;
constexpr size_t WFF = (size_t)L * FF * D;
__device__ __align__(256) __half g_scoresh[BHSS];
__device__ __align__(256) __half g_wqf[WSZ], g_wkf[WSZ], g_wvf[WSZ], g_wof[WSZ];
__device__ __align__(256) __half g_wif[WFF], g_wdf[WFF];
__device__ __align__(256) __half g_xf[BSD], g_ctxf[BSD], g_attnf[BSD];
__device__ __align__(256) __half g_fff[BS * FF];
__device__ __align__(256) __half g_qf[BSD], g_kf[BSD], g_vf[BSD];
__device__ __align__(256) __half g_pf[BHSS];
__device__ __align__(256) __half g_ptf[BHS * NRELP];
__device__ __align__(256) __half g_tabf[160 * 64];
__device__ __align__(256) __half g_tTf[64 * NRELP];

// ---------------- helpers ----------------
__device__ __forceinline__ float block_sum_fast(float v, float* red, float* bc) {
    int lane = threadIdx.x & 31, wid = threadIdx.x >> 5;
    #pragma unroll
    for (int o = 16; o > 0; o >>= 1) v += __shfl_xor_sync(0xffffffffu, v, o);
    if (lane == 0) red[wid] = v;
    __syncthreads();
    if (wid == 0) {
        float s = (lane < 8) ? red[lane] : 0.f;
        #pragma unroll
        for (int o = 4; o > 0; o >>= 1) s += __shfl_xor_sync(0xffffffffu, s, o);
        if (lane == 0) bc[0] = s;
    }
    __syncthreads();
    return bc[0];
}

__global__ void build_tables(const float* __restrict__ rel,
                             __half* __restrict__ tabf, __half* __restrict__ tTf)
{
    int i = blockIdx.x * 256 + threadIdx.x;
    if (i >= 160 * 64) return;
    int j = i / 64, d = i % 64;
    float v = (j < NREL) ? rel[((size_t)128 * S + (64 + j)) * DH + d] : 0.f;
    __half h = __float2half_rn(v);
    tabf[j * 64 + d] = h;
    if (j < NRELP) tTf[d * NRELP + j] = h;
}

__global__ __launch_bounds__(256) void conv_f16(
    const float* __restrict__ in, __half* __restrict__ o, int n4)
{
    int i = blockIdx.x * 256 + threadIdx.x;
    if (i >= n4) return;
    float4 v = ((const float4*)in)[i];
    __half2* op = (__half2*)o;
    op[i * 2 + 0] = __floats2half2_rn(v.x, v.y);
    op[i * 2 + 1] = __floats2half2_rn(v.z, v.w);
}

// ---------------- mma primitives ----------------
__device__ __forceinline__ void mma16816h(float* d, const uint32_t* a, const uint32_t* b) {
    asm volatile(
        "mma.sync.aligned.m16n8k16.row.col.f32.f16.f16.f32 "
        "{%0,%1,%2,%3}, {%4,%5,%6,%7}, {%8,%9}, {%0,%1,%2,%3};\n"
        : "+f"(d[0]), "+f"(d[1]), "+f"(d[2]), "+f"(d[3])
        : "r"(a[0]), "r"(a[1]), "r"(a[2]), "r"(a[3]), "r"(b[0]), "r"(b[1]));
}
__device__ __forceinline__ void ldsm4(uint32_t* r, uint32_t addr) {
    asm volatile("ldmatrix.sync.aligned.m8n8.x4.shared.b16 {%0,%1,%2,%3}, [%4];\n"
        : "=r"(r[0]), "=r"(r[1]), "=r"(r[2]), "=r"(r[3]) : "r"(addr));
}
__device__ __forceinline__ void ldsm4t(uint32_t* r, uint32_t addr) {
    asm volatile("ldmatrix.sync.aligned.m8n8.x4.trans.shared.b16 {%0,%1,%2,%3}, [%4];\n"
        : "=r"(r[0]), "=r"(r[1]), "=r"(r[2]), "=r"(r[3]) : "r"(addr));
}
__device__ __forceinline__ void cp16(uint32_t dst, const void* src) {
    asm volatile("cp.async.cg.shared.global [%0], [%1], 16;\n" :: "r"(dst), "l"(src));
}
__device__ __forceinline__ void cp_commit() { asm volatile("cp.async.commit_group;\n"); }
__device__ __forceinline__ void cp_wait1() { asm volatile("cp.async.wait_group 1;\n" ::: "memory"); }
__device__ __forceinline__ void cp_wait0() { asm volatile("cp.async.wait_group 0;\n" ::: "memory"); }
__device__ __forceinline__ uint32_t smem_u32(const void* p) {
    return (uint32_t)__cvta_generic_to_shared(p);
}

// ======================================================================
// fp16 single-term pipelined MMA GEMM NT (128x128 tile)
// ======================================================================
constexpr int FSTR = 40;
constexpr int FARR = 128 * FSTR * 2;
constexpr int FSTG = 2 * FARR;
constexpr int FNSTG = 3;
constexpr int F_SMEM = FNSTG * FSTG;

struct F16Targets {
    const __half* w[3];
    const float* bias[3];
    const float* res[3];
    float* c[3];
    __half* cf[3];
};

__global__ __launch_bounds__(256, 2) void gemm_f16_pipe(
    const __half* __restrict__ A, F16Targets tg, int M, int N, int K, int act)
{
    extern __shared__ __align__(16) char dsm[];
    const uint32_t sbase = smem_u32(dsm);
    const int z = blockIdx.z;
    const __half* W = tg.w[z];

    const int bm = blockIdx.y * 128, bn = blockIdx.x * 128;
    const int t = threadIdx.x, lane = t & 31, w = t >> 5;
    const int wm = (w & 1) * 64, wn = (w >> 1) * 32;

    float acc[4][4][4];
    #pragma unroll
    for (int i = 0; i < 4; i++)
        #pragma unroll
        for (int j = 0; j < 4; j++)
            #pragma unroll
            for (int r = 0; r < 4; r++) acc[i][j][r] = 0.f;

    uint32_t aoff[4], boff[2];
    #pragma unroll
    for (int mi = 0; mi < 4; mi++)
        aoff[mi] = (uint32_t)(((wm + mi * 16 + (lane & 15)) * FSTR + ((lane >> 4) << 3)) * 2);
    #pragma unroll
    for (int ni2 = 0; ni2 < 2; ni2++)
        boff[ni2] = (uint32_t)(((wn + ni2 * 16 + (lane & 7) + ((lane >> 4) << 3)) * FSTR
                               + (((lane >> 3) & 1) << 3)) * 2);

    const int nk = K / 32;
    const int r0 = t >> 2, c0 = t & 3;
    const int r1 = (t + 256) >> 2, c1 = (t + 256) & 3;
    const uint32_t d0 = (uint32_t)((r0 * FSTR + c0 * 8) * 2);
    const uint32_t d1 = (uint32_t)((r1 * FSTR + c1 * 8) * 2);

    auto issue = [&](int c) {
        if (c < nk) {
            const uint32_t base = sbase + (c % FNSTG) * FSTG;
            const size_t k0 = (size_t)c * 32;
            cp16(base + d0,        A + (size_t)(bm + r0) * K + k0 + c0 * 8);
            cp16(base + d1,        A + (size_t)(bm + r1) * K + k0 + c1 * 8);
            cp16(base + FARR + d0, W + (size_t)(bn + r0) * K + k0 + c0 * 8);
            cp16(base + FARR + d1, W + (size_t)(bn + r1) * K + k0 + c1 * 8);
        }
        cp_commit();
    };
    issue(0);
    issue(1);

    for (int kt = 0; kt < nk; kt++) {
        cp_wait1();
        __syncthreads();
        issue(kt + 2);

        const uint32_t sb = sbase + (kt % FNSTG) * FSTG;
        #pragma unroll
        for (int kk2 = 0; kk2 < 2; kk2++) {
            const uint32_t ko = kk2 * 32;
            uint32_t ah[4][4], bh[4][2];
            #pragma unroll
            for (int mi = 0; mi < 4; mi++)
                ldsm4(ah[mi], sb + aoff[mi] + ko);
            #pragma unroll
            for (int ni2 = 0; ni2 < 2; ni2++) {
                uint32_t t4[4];
                ldsm4(t4, sb + FARR + boff[ni2] + ko);
                bh[ni2 * 2][0] = t4[0]; bh[ni2 * 2][1] = t4[1];
                bh[ni2 * 2 + 1][0] = t4[2]; bh[ni2 * 2 + 1][1] = t4[3];
            }
            #pragma unroll
            for (int mi = 0; mi < 4; mi++)
                #pragma unroll
                for (int ni = 0; ni < 4; ni++)
                    mma16816h(acc[mi][ni], ah[mi], bh[ni]);
        }
        __syncthreads();
    }

    const float* bias = tg.bias[z];
    const float* res  = tg.res[z];
    float* Cp = tg.c[z];
    __half* Cf = tg.cf[z];

    #pragma unroll
    for (int mi = 0; mi < 4; mi++) {
        int m0 = bm + wm + mi * 16 + (lane >> 2);
        #pragma unroll
        for (int ni = 0; ni < 4; ni++) {
            int n = bn + wn + ni * 8 + (lane & 3) * 2;
            float2 v0 = make_float2(acc[mi][ni][0], acc[mi][ni][1]);
            float2 v1 = make_float2(acc[mi][ni][2], acc[mi][ni][3]);
            if (bias) {
                float2 bv = *(const float2*)&bias[n];
                v0.x += bv.x; v0.y += bv.y; v1.x += bv.x; v1.y += bv.y;
            }
            if (res) {
                float2 rr0 = *(const float2*)&res[(size_t)m0 * N + n];
                float2 rr1 = *(const float2*)&res[(size_t)(m0 + 8) * N + n];
                v0.x += rr0.x; v0.y += rr0.y; v1.x += rr1.x; v1.y += rr1.y;
            }
            if (act == 1) {
                v0.x = 0.5f * v0.x * (1.f + erff(v0.x * 0.70710678118654752f));
                v0.y = 0.5f * v0.y * (1.f + erff(v0.y * 0.70710678118654752f));
                v1.x = 0.5f * v1.x * (1.f + erff(v1.x * 0.70710678118654752f));
                v1.y = 0.5f * v1.y * (1.f + erff(v1.y * 0.70710678118654752f));
            }
            if (Cp) {
                *(float2*)&Cp[(size_t)m0 * N + n] = v0;
                *(float2*)&Cp[(size_t)(m0 + 8) * N + n] = v1;
            }
            if (Cf) {
                *(__half2*)&Cf[(size_t)m0 * N + n] = __floats2half2_rn(v0.x, v0.y);
                *(__half2*)&Cf[(size_t)(m0 + 8) * N + n] = __floats2half2_rn(v1.x, v1.y);
            }
        }
    }
}

// ======================================================================
// Split-K=2 fp16 GEMM NT (128x128 tile). blockIdx.z selects K-slice;
// slice z covers [z*Kslice, (z+1)*Kslice). Plain fp32 partial output.
// ======================================================================
__global__ __launch_bounds__(256, 2) void gemm_f16_splitk(
    const __half* __restrict__ A, const __half* __restrict__ W,
    float* __restrict__ C0, float* __restrict__ C1,
    int M, int N, int Kfull, int Kslice)
{
    extern __shared__ __align__(16) char dsm[];
    const uint32_t sbase = smem_u32(dsm);
    const int z = blockIdx.z;
    const int kbase = z * Kslice;
    float* Cp = z ? C1 : C0;

    const int bm = blockIdx.y * 128, bn = blockIdx.x * 128;
    const int t = threadIdx.x, lane = t & 31, w = t >> 5;
    const int wm = (w & 1) * 64, wn = (w >> 1) * 32;

    float acc[4][4][4];
    #pragma unroll
    for (int i = 0; i < 4; i++)
        #pragma unroll
        for (int j = 0; j < 4; j++)
            #pragma unroll
            for (int r = 0; r < 4; r++) acc[i][j][r] = 0.f;

    uint32_t aoff[4], boff[2];
    #pragma unroll
    for (int mi = 0; mi < 4; mi++)
        aoff[mi] = (uint32_t)(((wm + mi * 16 + (lane & 15)) * FSTR + ((lane >> 4) << 3)) * 2);
    #pragma unroll
    for (int ni2 = 0; ni2 < 2; ni2++)
        boff[ni2] = (uint32_t)(((wn + ni2 * 16 + (lane & 7) + ((lane >> 4) << 3)) * FSTR
                               + (((lane >> 3) & 1) << 3)) * 2);

    const int nk = Kslice / 32;
    const int r0 = t >> 2, c0 = t & 3;
    const int r1 = (t + 256) >> 2, c1 = (t + 256) & 3;
    const uint32_t d0 = (uint32_t)((r0 * FSTR + c0 * 8) * 2);
    const uint32_t d1 = (uint32_t)((r1 * FSTR + c1 * 8) * 2);

    auto issue = [&](int c) {
        if (c < nk) {
            const uint32_t base = sbase + (c % FNSTG) * FSTG;
            const size_t k0 = (size_t)kbase + (size_t)c * 32;
            cp16(base + d0,        A + (size_t)(bm + r0) * Kfull + k0 + c0 * 8);
            cp16(base + d1,        A + (size_t)(bm + r1) * Kfull + k0 + c1 * 8);
            cp16(base + FARR + d0, W + (size_t)(bn + r0) * Kfull + k0 + c0 * 8);
            cp16(base + FARR + d1, W + (size_t)(bn + r1) * Kfull + k0 + c1 * 8);
        }
        cp_commit();
    };
    issue(0);
    issue(1);

    for (int kt = 0; kt < nk; kt++) {
        cp_wait1();
        __syncthreads();
        issue(kt + 2);

        const uint32_t sb = sbase + (kt % FNSTG) * FSTG;
        #pragma unroll
        for (int kk2 = 0; kk2 < 2; kk2++) {
            const uint32_t ko = kk2 * 32;
            uint32_t ah[4][4], bh[4][2];
            #pragma unroll
            for (int mi = 0; mi < 4; mi++)
                ldsm4(ah[mi], sb + aoff[mi] + ko);
            #pragma unroll
            for (int ni2 = 0; ni2 < 2; ni2++) {
                uint32_t t4[4];
                ldsm4(t4, sb + FARR + boff[ni2] + ko);
                bh[ni2 * 2][0] = t4[0]; bh[ni2 * 2][1] = t4[1];
                bh[ni2 * 2 + 1][0] = t4[2]; bh[ni2 * 2 + 1][1] = t4[3];
            }
            #pragma unroll
            for (int mi = 0; mi < 4; mi++)
                #pragma unroll
                for (int ni = 0; ni < 4; ni++)
                    mma16816h(acc[mi][ni], ah[mi], bh[ni]);
        }
        __syncthreads();
    }

    #pragma unroll
    for (int mi = 0; mi < 4; mi++) {
        int m0 = bm + wm + mi * 16 + (lane >> 2);
        #pragma unroll
        for (int ni = 0; ni < 4; ni++) {
            int n = bn + wn + ni * 8 + (lane & 3) * 2;
            *(float2*)&Cp[(size_t)m0 * N + n] =
                make_float2(acc[mi][ni][0], acc[mi][ni][1]);
            *(float2*)&Cp[(size_t)(m0 + 8) * N + n] =
                make_float2(acc[mi][ni][2], acc[mi][ni][3]);
        }
    }
}

// ======================================================================
// qtab fp16
// ======================================================================
constexpr int QT_STR = 72;
constexpr int QT_A = 128 * QT_STR * 2;
constexpr int QT_B = 160 * QT_STR * 2;
constexpr int QT_SMEM = QT_A + QT_B;

__global__ __launch_bounds__(256) void qtab_f16(
    const __half* __restrict__ Qf, const __half* __restrict__ Tf,
    float* __restrict__ qt)
{
    extern __shared__ __align__(16) char dsm[];
    __half* sA = (__half*)dsm;
    __half* sB = (__half*)(dsm + QT_A);
    const uint32_t bA = smem_u32(sA), bB = smem_u32(sB);

    const int bm = blockIdx.x * 128;
    const int t = threadIdx.x, lane = t & 31, w = t >> 5;
    const int wm = (w & 3) * 32, wn = (w >> 2) * 80;

    #pragma unroll
    for (int i = 0; i < 4; i++) {
        int s = t + i * 256;
        int row = s >> 3, c8 = s & 7;
        *(uint4*)&sA[row * QT_STR + c8 * 8] = *(const uint4*)&Qf[(size_t)(bm + row) * 64 + c8 * 8];
    }
    #pragma unroll
    for (int i = 0; i < 5; i++) {
        int s = t + i * 256;
        int row = s >> 3, c8 = s & 7;
        *(uint4*)&sB[row * QT_STR + c8 * 8] = *(const uint4*)&Tf[row * 64 + c8 * 8];
    }
    __syncthreads();

    float acc[2][10][4];
    #pragma unroll
    for (int i = 0; i < 2; i++)
        #pragma unroll
        for (int j = 0; j < 10; j++)
            #pragma unroll
            for (int r = 0; r < 4; r++) acc[i][j][r] = 0.f;

    uint32_t aoff[2], boff[5];
    #pragma unroll
    for (int mi = 0; mi < 2; mi++)
        aoff[mi] = (uint32_t)(((wm + mi * 16 + (lane & 15)) * QT_STR + ((lane >> 4) << 3)) * 2);
    #pragma unroll
    for (int ni2 = 0; ni2 < 5; ni2++)
        boff[ni2] = (uint32_t)(((wn + ni2 * 16 + (lane & 7) + ((lane >> 4) << 3)) * QT_STR
                               + (((lane >> 3) & 1) << 3)) * 2);

    #pragma unroll
    for (int kc = 0; kc < 4; kc++) {
        uint32_t ko = kc * 32;
        uint32_t ah[2][4];
        #pragma unroll
        for (int mi = 0; mi < 2; mi++)
            ldsm4(ah[mi], bA + aoff[mi] + ko);
        #pragma unroll
        for (int ni2 = 0; ni2 < 5; ni2++) {
            uint32_t t4[4];
            ldsm4(t4, bB + boff[ni2] + ko);
            uint32_t b0[2] = {t4[0], t4[1]}, b1[2] = {t4[2], t4[3]};
            #pragma unroll
            for (int mi = 0; mi < 2; mi++) {
                mma16816h(acc[mi][ni2 * 2], ah[mi], b0);
                mma16816h(acc[mi][ni2 * 2 + 1], ah[mi], b1);
            }
        }
    }

    #pragma unroll
    for (int mi = 0; mi < 2; mi++)
        #pragma unroll
        for (int rr = 0; rr < 2; rr++) {
            int m0 = bm + wm + mi * 16 + (lane >> 2) + rr * 8;
            #pragma unroll
            for (int ni = 0; ni < 10; ni++) {
                int n = wn + ni * 8 + (lane & 3) * 2;
                if (n < NREL)     qt[(size_t)m0 * NREL + n]     = acc[mi][ni][rr * 2 + 0];
                if (n + 1 < NREL) qt[(size_t)m0 * NREL + n + 1] = acc[mi][ni][rr * 2 + 1];
            }
        }
}

// ======================================================================
// ctx_rel fp16
// ======================================================================
constexpr int CR_ASTR = 56;
constexpr int CR_BSTR = 152;
constexpr int CR_A = 128 * CR_ASTR * 2;
constexpr int CR_B = 64 * CR_BSTR * 2;
constexpr int CR_SMEM = CR_A + CR_B;

__global__ __launch_bounds__(256) void ctx_rel_f16(
    const __half* __restrict__ Pf, const __half* __restrict__ Tf,
    float* __restrict__ ctx)
{
    extern __shared__ __align__(16) char dsm[];
    __half* sA = (__half*)dsm;
    __half* sB = (__half*)(dsm + CR_A);
    const uint32_t bA = smem_u32(sA), bB = smem_u32(sB);

    const int bm = blockIdx.x * 128;
    const int t = threadIdx.x, lane = t & 31, w = t >> 5;
    const int wm = (w & 3) * 32, wn = (w >> 2) * 32;

    for (int s = t; s < 1152; s += 256) {
        int row = s / 18, c8 = s % 18;
        *(uint4*)&sB[row * CR_BSTR + c8 * 8] = *(const uint4*)&Tf[row * NRELP + c8 * 8];
    }

    float acc[2][4][4];
    #pragma unroll
    for (int i = 0; i < 2; i++)
        #pragma unroll
        for (int j = 0; j < 4; j++)
            #pragma unroll
            for (int r = 0; r < 4; r++) acc[i][j][r] = 0.f;

    uint32_t aoff[2], boff[2];
    #pragma unroll
    for (int mi = 0; mi < 2; mi++)
        aoff[mi] = (uint32_t)(((wm + mi * 16 + (lane & 15)) * CR_ASTR + ((lane >> 4) << 3)) * 2);
    #pragma unroll
    for (int ni2 = 0; ni2 < 2; ni2++)
        boff[ni2] = (uint32_t)(((wn + ni2 * 16 + (lane & 7) + ((lane >> 4) << 3)) * CR_BSTR
                               + (((lane >> 3) & 1) << 3)) * 2);

    for (int c = 0; c < 3; c++) {
        __syncthreads();
        #pragma unroll
        for (int i = 0; i < 3; i++) {
            int s = t + i * 256;
            int row = s / 6, c8 = s % 6;
            size_t src = (size_t)(bm + row) * NRELP + c * 48 + c8 * 8;
            *(uint4*)&sA[row * CR_ASTR + c8 * 8] = *(const uint4*)&Pf[src];
        }
        __syncthreads();
        #pragma unroll
        for (int kc = 0; kc < 3; kc++) {
            uint32_t kaoff = kc * 32;
            uint32_t kboff = (uint32_t)(c * 96 + kc * 32);
            uint32_t ah[2][4];
            #pragma unroll
            for (int mi = 0; mi < 2; mi++)
                ldsm4(ah[mi], bA + aoff[mi] + kaoff);
            #pragma unroll
            for (int ni2 = 0; ni2 < 2; ni2++) {
                uint32_t t4[4];
                ldsm4(t4, bB + boff[ni2] + kboff);
                uint32_t b0[2] = {t4[0], t4[1]}, b1[2] = {t4[2], t4[3]};
                #pragma unroll
                for (int mi = 0; mi < 2; mi++) {
                    mma16816h(acc[mi][ni2 * 2], ah[mi], b0);
                    mma16816h(acc[mi][ni2 * 2 + 1], ah[mi], b1);
                }
            }
        }
    }

    #pragma unroll
    for (int mi = 0; mi < 2; mi++)
        #pragma unroll
        for (int rr = 0; rr < 2; rr++) {
            int m0 = bm + wm + mi * 16 + (lane >> 2) + rr * 8;
            #pragma unroll
            for (int ni = 0; ni < 4; ni++) {
                int n = wn + ni * 8 + (lane & 3) * 2;
                float2 v = make_float2(acc[mi][ni][rr * 2 + 0], acc[mi][ni][rr * 2 + 1]);
                *(float2*)&ctx[(size_t)m0 * 64 + n] = v;
            }
        }
}

// ======================================================================
// Scores fp16 -> fp16 score storage
// ======================================================================
constexpr int QSTR = 40;
constexpr int SC_ARR = 128 * QSTR * 2;
constexpr int SC_STG = 2 * SC_ARR;
constexpr int SC_SMEM = 2 * SC_STG;

__global__ __launch_bounds__(256) void scores_f16(
    const __half* __restrict__ Qf, const __half* __restrict__ Kf,
    const float* __restrict__ qtab, const int* __restrict__ mask,
    __half* __restrict__ scores)
{
    extern __shared__ __align__(16) char dsm[];
    const uint32_t sbase = smem_u32(dsm);
    const int bh = blockIdx.z, b = bh / H, h = bh % H;
    const int q0 = blockIdx.y * 128, k0b = blockIdx.x * 128;
    const int t = threadIdx.x, lane = t & 31, w = t >> 5;
    const int wm = (w & 1) * 64, wn = (w >> 1) * 32;

    float acc[4][4][4];
    #pragma unroll
    for (int i = 0; i < 4; i++)
        #pragma unroll
        for (int j = 0; j < 4; j++)
            #pragma unroll
            for (int r = 0; r < 4; r++) acc[i][j][r] = 0.f;

    uint32_t aoff[4], boff[2];
    #pragma unroll
    for (int mi = 0; mi < 4; mi++)
        aoff[mi] = (uint32_t)(((wm + mi * 16 + (lane & 15)) * QSTR + ((lane >> 4) << 3)) * 2);
    #pragma unroll
    for (int ni2 = 0; ni2 < 2; ni2++)
        boff[ni2] = (uint32_t)(((wn + ni2 * 16 + (lane & 7) + ((lane >> 4) << 3)) * QSTR
                               + (((lane >> 3) & 1) << 3)) * 2);

    auto issue = [&](int kt) {
        uint32_t base = sbase + kt * SC_STG;
        #pragma unroll
        for (int i = 0; i < 2; i++) {
            int idx = t * 2 + i;
            int row = idx >> 2, cseg = (idx & 3) * 8;
            size_t qsrc = ((size_t)(b * S) + q0 + row) * D + h * DH + kt * 32 + cseg;
            size_t ksrc = ((size_t)(b * S) + k0b + row) * D + h * DH + kt * 32 + cseg;
            uint32_t d = base + (uint32_t)((row * QSTR + cseg) * 2);
            cp16(d,          Qf + qsrc);
            cp16(d + SC_ARR, Kf + ksrc);
        }
        cp_commit();
    };
    issue(0);
    issue(1);

    for (int kt = 0; kt < 2; kt++) {
        if (kt == 0) cp_wait1(); else cp_wait0();
        __syncthreads();
        const uint32_t sb = sbase + kt * SC_STG;
        #pragma unroll
        for (int kk2 = 0; kk2 < 2; kk2++) {
            uint32_t koffb = kk2 * 32;
            uint32_t ah[4][4], bh2[4][2];
            #pragma unroll
            for (int mi = 0; mi < 4; mi++)
                ldsm4(ah[mi], sb + aoff[mi] + koffb);
            #pragma unroll
            for (int ni2 = 0; ni2 < 2; ni2++) {
                uint32_t t4[4];
                ldsm4(t4, sb + SC_ARR + boff[ni2] + koffb);
                bh2[ni2 * 2][0] = t4[0]; bh2[ni2 * 2][1] = t4[1];
                bh2[ni2 * 2 + 1][0] = t4[2]; bh2[ni2 * 2 + 1][1] = t4[3];
            }
            #pragma unroll
            for (int mi = 0; mi < 4; mi++)
                #pragma unroll
                for (int ni = 0; ni < 4; ni++)
                    mma16816h(acc[mi][ni], ah[mi], bh2[ni]);
        }
    }

    #pragma unroll
    for (int mi = 0; mi < 4; mi++) {
        #pragma unroll
        for (int rr = 0; rr < 2; rr++) {
            int q = q0 + wm + mi * 16 + (lane >> 2) + rr * 8;
            const float* qtr = qtab + (((size_t)b * S + q) * H + h) * NREL;
            size_t rowb = ((size_t)bh * S + q) * S;
            #pragma unroll
            for (int ni = 0; ni < 4; ni++) {
                int k = k0b + wn + ni * 8 + (lane & 3) * 2;
                float vx = acc[mi][ni][rr * 2 + 0];
                float vy = acc[mi][ni][rr * 2 + 1];
                int r0 = k - q; r0 = r0 < -64 ? -64 : (r0 > 64 ? 64 : r0);
                int r1 = k + 1 - q; r1 = r1 < -64 ? -64 : (r1 > 64 ? 64 : r1);
                float mb0 = (1.f - (float)mask[b * S + k]) * -10000.f;
                float mb1 = (1.f - (float)mask[b * S + k + 1]) * -10000.f;
                float ox = (vx + qtr[r0 + 64]) * SCALE + mb0;
                float oy = (vy + qtr[r1 + 64]) * SCALE + mb1;
                *(__half2*)&scores[rowb + k] = __floats2half2_rn(ox, oy);
            }
        }
    }
}

// ======================================================================
// ctx_pv fp16
// ======================================================================
constexpr int VSTR = 72;
constexpr int PV_P = 128 * QSTR * 2;
constexpr int PV_V = 32 * VSTR * 2;
constexpr int PV_STG = PV_P + PV_V;
constexpr int PV_NSTG = 3;
constexpr int PV_SMEM = PV_NSTG * PV_STG;

__global__ __launch_bounds__(256) void ctx_pv_f16(
    const __half* __restrict__ Pf, const __half* __restrict__ Vf,
    const float* __restrict__ ctxin, __half* __restrict__ outf)
{
    extern __shared__ __align__(16) char dsm[];
    const uint32_t sbase = smem_u32(dsm);
    const int bh = blockIdx.z, b = bh / H, h = bh % H;
    const int q0 = blockIdx.x * 128;
    const int t = threadIdx.x, lane = t & 31, w = t >> 5;
    const int wm = (w & 3) * 32, wn = (w >> 2) * 32;

    float acc[2][4][4];
    #pragma unroll
    for (int i = 0; i < 2; i++)
        #pragma unroll
        for (int j = 0; j < 4; j++)
            #pragma unroll
            for (int r = 0; r < 4; r++) acc[i][j][r] = 0.f;

    uint32_t aoff[2];
    #pragma unroll
    for (int mi = 0; mi < 2; mi++)
        aoff[mi] = (uint32_t)(((wm + mi * 16 + (lane & 15)) * QSTR + ((lane >> 4) << 3)) * 2);

    const int nk = S / 32;

    auto issue = [&](int kt, int slot) {
        if (kt < nk) {
            uint32_t base = sbase + slot * PV_STG;
            #pragma unroll
            for (int i = 0; i < 2; i++) {
                int idx = t * 2 + i;
                int row = idx >> 2, cseg = (idx & 3) * 8;
                size_t psrc = ((size_t)bh * S + q0 + row) * S + kt * 32 + cseg;
                cp16(base + (uint32_t)((row * QSTR + cseg) * 2), Pf + psrc);
            }
            {
                int row = t >> 3, cseg = (t & 7) * 8;
                size_t vsrc = ((size_t)(b * S) + kt * 32 + row) * D + h * DH + cseg;
                cp16(base + PV_P + (uint32_t)((row * VSTR + cseg) * 2), Vf + vsrc);
            }
        }
        cp_commit();
    };
    issue(0, 0);
    issue(1, 1);

    for (int kt = 0; kt < nk; kt++) {
        cp_wait1();
        __syncthreads();
        issue(kt + 2, (kt + 2) % PV_NSTG);

        const uint32_t sb = sbase + (kt % PV_NSTG) * PV_STG;
        #pragma unroll
        for (int kk2 = 0; kk2 < 2; kk2++) {
            uint32_t koffb = kk2 * 32;
            uint32_t ah[2][4], bh2[4][2];
            #pragma unroll
            for (int mi = 0; mi < 2; mi++)
                ldsm4(ah[mi], sb + aoff[mi] + koffb);
            #pragma unroll
            for (int ni2 = 0; ni2 < 2; ni2++) {
                uint32_t vaddr = (uint32_t)(((kk2 * 16 + (lane & 15)) * VSTR
                                 + wn + ni2 * 16 + (lane >> 4) * 8) * 2);
                uint32_t t4[4];
                ldsm4t(t4, sb + PV_P + vaddr);
                bh2[ni2 * 2][0] = t4[0]; bh2[ni2 * 2][1] = t4[1];
                bh2[ni2 * 2 + 1][0] = t4[2]; bh2[ni2 * 2 + 1][1] = t4[3];
            }
            #pragma unroll
            for (int mi = 0; mi < 2; mi++)
                #pragma unroll
                for (int ni = 0; ni < 4; ni++)
                    mma16816h(acc[mi][ni], ah[mi], bh2[ni]);
        }
        __syncthreads();
    }

    #pragma unroll
    for (int mi = 0; mi < 2; mi++) {
        #pragma unroll
        for (int rr = 0; rr < 2; rr++) {
            int q = q0 + wm + mi * 16 + (lane >> 2) + rr * 8;
            size_t rb = ((size_t)(b * S) + q) * D + h * DH;
            #pragma unroll
            for (int ni = 0; ni < 4; ni++) {
                int d = wn + ni * 8 + (lane & 3) * 2;
                float2 cur = *(const float2*)&ctxin[rb + d];
                cur.x += acc[mi][ni][rr * 2 + 0];
                cur.y += acc[mi][ni][rr * 2 + 1];
                *(__half2*)&outf[rb + d] = __floats2half2_rn(cur.x, cur.y);
            }
        }
    }
}

// ---------------- embedding + LN ----------------
__global__ __launch_bounds__(256) void embed_ln(
    const int* __restrict__ ids, const int* __restrict__ tti,
    const float* __restrict__ we, const float* __restrict__ te,
    const float* __restrict__ w, const float* __restrict__ bb,
    float* __restrict__ out, __half* __restrict__ of)
{
    __shared__ float red[8];
    __shared__ float bc0[1], bc1[1];
    int m = blockIdx.x, t = threadIdx.x;
    int id = ids[m], t2 = tti[m];
    const float* wr = we + (size_t)id * D;
    const float* tr = te + (size_t)t2 * D;
    float vals[3]; float s = 0.f;
    #pragma unroll
    for (int i = 0; i < 3; i++) { int d = t + i * 256; vals[i] = wr[d] + tr[d]; s += vals[i]; }
    float mean = block_sum_fast(s, red, bc0) * (1.f / D);
    float vs = 0.f;
    #pragma unroll
    for (int i = 0; i < 3; i++) { float dd = vals[i] - mean; vs += dd * dd; }
    float var = block_sum_fast(vs, red, bc1) * (1.f / D);
    float rstd = rsqrtf(var + LN_EPS);
    #pragma unroll
    for (int i = 0; i < 3; i++) {
        int d = t + i * 256;
        float v = (vals[i] - mean) * rstd * w[d] + bb[d];
        out[(size_t)m * D + d] = v;
        of[(size_t)m * D + d] = __float2half_rn(v);
    }
}

// LN over (tA + tB + bias + res): split-K combine fused into LayerNorm.
__global__ __launch_bounds__(256) void ln_sum2(
    const float* __restrict__ ta, const float* __restrict__ tb,
    const float* __restrict__ bias, const float* __restrict__ res,
    const float* __restrict__ w, const float* __restrict__ bb,
    float* __restrict__ out, __half* __restrict__ of)
{
    __shared__ float red[8];
    __shared__ float bc0[1], bc1[1];
    int m = blockIdx.x, t = threadIdx.x;
    size_t rb = (size_t)m * D;
    float vals[3]; float s = 0.f;
    #pragma unroll
    for (int i = 0; i < 3; i++) {
        int d = t + i * 256;
        vals[i] = ta[rb + d] + tb[rb + d] + bias[d] + res[rb + d];
        s += vals[i];
    }
    float mean = block_sum_fast(s, red, bc0) * (1.f / D);
    float vs = 0.f;
    #pragma unroll
    for (int i = 0; i < 3; i++) { float dd = vals[i] - mean; vs += dd * dd; }
    float var = block_sum_fast(vs, red, bc1) * (1.f / D);
    float rstd = rsqrtf(var + LN_EPS);
    #pragma unroll
    for (int i = 0; i < 3; i++) {
        int d = t + i * 256;
        float v = (vals[i] - mean) * rstd * w[d] + bb[d];
        out[rb + d] = v;
        of[rb + d] = __float2half_rn(v);
    }
}

// ---------------- warp-per-row softmax (fp16 score input) ----------------
__global__ __launch_bounds__(256) void softmax_warp(
    const __half* __restrict__ scores,
    __half* __restrict__ pf, __half* __restrict__ ptf)
{
    __shared__ float srow[8][512];
    const int w = threadIdx.x >> 5, lane = threadIdx.x & 31;
    const int row = blockIdx.x * 8 + w;
    const int q = row % S, bh = row / S;
    const int b = bh / H, h = bh % H;
    const __half* sr = scores + (size_t)row * S;

    float2 v[8];
    float m = -1e30f;
    #pragma unroll
    for (int i = 0; i < 8; i++) {
        __half2 h2 = *(const __half2*)&sr[lane * 2 + 64 * i];
        v[i] = __half22float2(h2);
        m = fmaxf(m, fmaxf(v[i].x, v[i].y));
    }
    #pragma unroll
    for (int o = 16; o > 0; o >>= 1) m = fmaxf(m, __shfl_xor_sync(0xffffffffu, m, o));

    float s = 0.f;
    #pragma unroll
    for (int i = 0; i < 8; i++) {
        v[i].x = expf(v[i].x - m); v[i].y = expf(v[i].y - m);
        s += v[i].x + v[i].y;
    }
    #pragma unroll
    for (int o = 16; o > 0; o >>= 1) s += __shfl_xor_sync(0xffffffffu, s, o);
    float inv = 1.f / s;

    size_t rb = (size_t)row * S;
    float left = 0.f, right = 0.f;
    #pragma unroll
    for (int i = 0; i < 8; i++) {
        int k = lane * 2 + 64 * i;
        float p0 = v[i].x * inv, p1 = v[i].y * inv;
        srow[w][k] = p0; srow[w][k + 1] = p1;
        *(__half2*)&pf[rb + k] = __floats2half2_rn(p0, p1);
        if (k <= q - 64)     left += p0;
        if (k + 1 <= q - 64) left += p1;
        if (k >= q + 64)     right += p0;
        if (k + 1 >= q + 64) right += p1;
    }
    #pragma unroll
    for (int o = 16; o > 0; o >>= 1) {
        left  += __shfl_xor_sync(0xffffffffu, left, o);
        right += __shfl_xor_sync(0xffffffffu, right, o);
    }
    __syncwarp();

    size_t pbase = ((size_t)(b * S + q) * H + h) * NRELP;
    if (lane == 0) {
        ptf[pbase]       = __float2half_rn(left);
        ptf[pbase + 128] = __float2half_rn(right);
    }
    if (lane < 15) ptf[pbase + 129 + lane] = __float2half_rn(0.f);
    #pragma unroll
    for (int jj = 0; jj < 4; jj++) {
        int j = 1 + lane + 32 * jj;
        if (j <= 127) {
            int k = q + j - 64;
            float p = (k >= 0 && k < S) ? srow[w][k] : 0.f;
            ptf[pbase + j] = __float2half_rn(p);
        }
    }
}

// ---------------- launch ----------------
extern "C" void kernel_launch(void* const* d_in, const int* in_sizes, int n_in,
                              void* d_out, int out_size)
{
    const int*   ids     = (const int*)d_in[0];
    const int*   amask   = (const int*)d_in[1];
    const int*   tti     = (const int*)d_in[2];
    const float* wemb    = (const float*)d_in[3];
    const float* temb    = (const float*)d_in[4];
    const float* elnw    = (const float*)d_in[5];
    const float* elnb    = (const float*)d_in[6];
    const float* qw      = (const float*)d_in[7];
    const float* qb      = (const float*)d_in[8];
    const float* kw      = (const float*)d_in[9];
    const float* kb      = (const float*)d_in[10];
    const float* vw      = (const float*)d_in[11];
    const float* vb      = (const float*)d_in[12];
    const float* rel     = (const float*)d_in[13];
    const float* ow      = (const float*)d_in[14];
    const float* ob      = (const float*)d_in[15];
    const float* alnw    = (const float*)d_in[16];
    const float* alnb    = (const float*)d_in[17];
    const float* iw      = (const float*)d_in[18];
    const float* ib      = (const float*)d_in[19];
    const float* dw      = (const float*)d_in[20];
    const float* db      = (const float*)d_in[21];
    const float* olnw    = (const float*)d_in[22];
    const float* olnb    = (const float*)d_in[23];
    float* out = (float*)d_out;

    float *x, *qt, *ctx, *tmpA, *tmpB, *attn;
    cudaGetSymbolAddress((void**)&x,    g_x);
    cudaGetSymbolAddress((void**)&qt,   g_qtab);
    cudaGetSymbolAddress((void**)&ctx,  g_ctx);
    cudaGetSymbolAddress((void**)&tmpA, g_tmpA);
    cudaGetSymbolAddress((void**)&tmpB, g_tmpB);
    cudaGetSymbolAddress((void**)&attn, g_attn);

    __half *scf;
    __half *wqf, *wkf, *wvf, *wof, *wif, *wdf, *xf, *ctxf, *attnf, *fff;
    __half *qf, *kf, *vf, *pf, *ptf, *tabf, *tTf;
    cudaGetSymbolAddress((void**)&scf, g_scoresh);
    cudaGetSymbolAddress((void**)&wqf, g_wqf);
    cudaGetSymbolAddress((void**)&wkf, g_wkf);
    cudaGetSymbolAddress((void**)&wvf, g_wvf);
    cudaGetSymbolAddress((void**)&wof, g_wof);
    cudaGetSymbolAddress((void**)&wif, g_wif);
    cudaGetSymbolAddress((void**)&wdf, g_wdf);
    cudaGetSymbolAddress((void**)&xf,   g_xf);
    cudaGetSymbolAddress((void**)&ctxf, g_ctxf);
    cudaGetSymbolAddress((void**)&attnf, g_attnf);
    cudaGetSymbolAddress((void**)&fff,  g_fff);
    cudaGetSymbolAddress((void**)&qf,  g_qf);
    cudaGetSymbolAddress((void**)&kf,  g_kf);
    cudaGetSymbolAddress((void**)&vf,  g_vf);
    cudaGetSymbolAddress((void**)&pf,  g_pf);
    cudaGetSymbolAddress((void**)&ptf, g_ptf);
    cudaGetSymbolAddress((void**)&tabf, g_tabf);
    cudaGetSymbolAddress((void**)&tTf,  g_tTf);

    cudaFuncSetAttribute(gemm_f16_pipe, cudaFuncAttributeMaxDynamicSharedMemorySize, F_SMEM);
    cudaFuncSetAttribute(gemm_f16_splitk, cudaFuncAttributeMaxDynamicSharedMemorySize, F_SMEM);
    cudaFuncSetAttribute(qtab_f16, cudaFuncAttributeMaxDynamicSharedMemorySize, QT_SMEM);
    cudaFuncSetAttribute(ctx_rel_f16, cudaFuncAttributeMaxDynamicSharedMemorySize, CR_SMEM);
    cudaFuncSetAttribute(scores_f16, cudaFuncAttributeMaxDynamicSharedMemorySize, SC_SMEM);
    cudaFuncSetAttribute(ctx_pv_f16, cudaFuncAttributeMaxDynamicSharedMemorySize, PV_SMEM);

    build_tables<<<(160 * 64 + 255) / 256, 256>>>(rel, tabf, tTf);
    embed_ln<<<(int)BS, 256>>>(ids, tti, wemb, temb, elnw, elnb, x, xf);

    {
        int n4 = (int)(WSZ / 4), g = (n4 + 255) / 256;
        conv_f16<<<g, 256>>>(qw, wqf, n4);
        conv_f16<<<g, 256>>>(kw, wkf, n4);
        conv_f16<<<g, 256>>>(vw, wvf, n4);
        conv_f16<<<g, 256>>>(ow, wof, n4);
        int n4f = (int)(WFF / 4), gf = (n4f + 255) / 256;
        conv_f16<<<gf, 256>>>(iw, wif, n4f);
        conv_f16<<<gf, 256>>>(dw, wdf, n4f);
    }

    const dim3 gQKV(D / 128, (int)(BS / 128), 3);
    const dim3 gSK(D / 128, (int)(BS / 128), 2);   // split-K grids (6,64,2)
    const dim3 gF1(FF / 128, (int)(BS / 128), 1);
    const dim3 gSC(S / 128, S / 128, B * H);
    const dim3 gPV(S / 128, 1, B * H);
    const int gRow = (int)(BS * H / 128);

    for (int l = 0; l < L; l++) {
        const size_t wo = (size_t)l * D * D;
        const size_t fo = (size_t)l * FF * D;

        F16Targets tq = {};
        tq.w[0] = wqf + wo; tq.bias[0] = qb + l * D; tq.cf[0] = qf;
        tq.w[1] = wkf + wo; tq.bias[1] = kb + l * D; tq.cf[1] = kf;
        tq.w[2] = wvf + wo; tq.bias[2] = vb + l * D; tq.cf[2] = vf;
        gemm_f16_pipe<<<gQKV, 256, F_SMEM>>>(xf, tq, (int)BS, D, D, 0);

        qtab_f16<<<gRow, 256, QT_SMEM>>>(qf, tabf, qt);

        scores_f16<<<gSC, 256, SC_SMEM>>>(qf, kf, qt, amask, scf);
        softmax_warp<<<(int)(BHS / 8), 256>>>(scf, pf, ptf);

        ctx_rel_f16<<<gRow, 256, CR_SMEM>>>(ptf, tTf, ctx);
        ctx_pv_f16<<<gPV, 256, PV_SMEM>>>(pf, vf, ctx, ctxf);

        // O-proj: split-K=2 (K=768 -> 2x384), combine in ln_sum2
        gemm_f16_splitk<<<gSK, 256, F_SMEM>>>(ctxf, wof + wo, tmpA, tmpB,
                                              (int)BS, D, D, D / 2);
        ln_sum2<<<(int)BS, 256>>>(tmpA, tmpB, ob + l * D, x,
                                  alnw + l * D, alnb + l * D, attn, attnf);

        F16Targets tf = {};
        tf.w[0] = wif + fo; tf.bias[0] = ib + l * FF; tf.cf[0] = fff;
        gemm_f16_pipe<<<gF1, 256, F_SMEM>>>(attnf, tf, (int)BS, FF, D, 1);

        // FFN2: split-K=2 (K=1536 -> 2x768), combine in ln_sum2
        gemm_f16_splitk<<<gSK, 256, F_SMEM>>>(fff, wdf + fo, tmpA, tmpB,
                                              (int)BS, D, FF, FF / 2);
        ln_sum2<<<(int)BS, 256>>>(tmpA, tmpB, db + l * D, attn,
                                  olnw + l * D, olnb + l * D,
                                  (l == L - 1) ? out : x, xf);
    }
}